// round 9
// baseline (speedup 1.0000x reference)
#include <cuda_runtime.h>

#define HIDDEN 256
#define INDIM  72
#define KG     328            // 72 (x) + 256 (h)
#define MTILE  16
#define NTH    512
#define USTR   336            // padded row stride in floats

// scratch offsets (floats)
#define OFF_WG4 0                          // [328][256][4] gate weights (i,f,g,o)
#define OFF_BG4 (KG*1024)                  // [256][4] fused gate bias
#define OFF_WI2 (OFF_BG4 + 1024)           // [256][256][2] init weights (Wh,Wc) k-major
#define OFF_WO3 (OFF_WI2 + HIDDEN*512)     // [256][96] output weights k-major, padded
#define OFF_BO3 (OFF_WO3 + HIDDEN*96)      // [96] output bias padded
#define NSCR    (OFF_BO3 + 96)

__device__ __align__(16) float g_scratch[NSCR];

__global__ void prep_kernel(const float* __restrict__ W_ih, const float* __restrict__ W_hh,
                            const float* __restrict__ b_ih, const float* __restrict__ b_hh,
                            const float* __restrict__ Wh,   const float* __restrict__ Wc,
                            const float* __restrict__ Wo,   const float* __restrict__ bo) {
    for (int i = blockIdx.x * blockDim.x + threadIdx.x; i < NSCR;
         i += gridDim.x * blockDim.x) {
        float v;
        if (i < OFF_BG4) {
            int g = i & 3, t = (i >> 2) & 255, k = i >> 10;
            int n = g * 256 + t;
            v = (k < INDIM) ? W_ih[n * INDIM + k] : W_hh[n * HIDDEN + (k - INDIM)];
        } else if (i < OFF_WI2) {
            int j = i - OFF_BG4;
            int n = (j & 3) * 256 + (j >> 2);
            v = b_ih[n] + b_hh[n];
        } else if (i < OFF_WO3) {
            int j = i - OFF_WI2;
            int e = j & 1, t = (j >> 1) & 255, k = j >> 9;
            v = e ? Wc[t * HIDDEN + k] : Wh[t * HIDDEN + k];
        } else if (i < OFF_BO3) {
            int j = i - OFF_WO3;
            int col = j % 96, n = j / 96;
            v = (col < INDIM) ? Wo[col * HIDDEN + n] : 0.0f;
        } else {
            int j = i - OFF_BO3;
            v = (j < INDIM) ? bo[j] : 0.0f;
        }
        g_scratch[i] = v;
    }
}

__device__ __forceinline__ float sigf(float x) {
    return __fdividef(1.0f, 1.0f + __expf(-x));
}
__device__ __forceinline__ float tanhfast(float x) {
    return fmaf(2.0f, sigf(2.0f * x), -1.0f);
}

__global__ void __launch_bounds__(NTH, 1)
lstm_main(const float* __restrict__ z, const float* __restrict__ bh,
          const float* __restrict__ bc, float* __restrict__ out) {
    __shared__ float u[MTILE][USTR];   // [m][k]: k<72 = x, 72..327 = h
    const int tid = threadIdx.x;
    const int m0 = blockIdx.x * MTILE;

    // ---- load z tile into h-region; zero x-region ----
    for (int i = tid; i < MTILE * HIDDEN; i += NTH) {
        int m = i >> 8, k = i & 255;
        u[m][INDIM + k] = z[(size_t)(m0 + m) * HIDDEN + k];
    }
    for (int i = tid; i < MTILE * INDIM; i += NTH)
        u[i / INDIM][i % INDIM] = 0.0f;
    __syncthreads();

    const int t = tid & 255;        // hidden / gate column owner
    const int rb = (tid >> 8) * 8;  // row base: 0 or 8

    // ---- init GEMM: h = z@Wh^T + bh ; c = z@Wc^T + bc ----
    float h[8], c[8];
    {
        float ha[8], ca[8];
        const float bhv = bh[t], bcv = bc[t];
#pragma unroll
        for (int m = 0; m < 8; m++) { ha[m] = bhv; ca[m] = bcv; }
        const float2* wi = (const float2*)(g_scratch + OFF_WI2);
#pragma unroll 2
        for (int k = 0; k < HIDDEN; k += 2) {
            float2 wa = wi[k * 256 + t];
            float2 wb = wi[(k + 1) * 256 + t];
#pragma unroll
            for (int m = 0; m < 8; m++) {
                float2 uv = *(const float2*)&u[rb + m][INDIM + k];
                ha[m] = fmaf(uv.x, wa.x, ha[m]);
                ca[m] = fmaf(uv.x, wa.y, ca[m]);
                ha[m] = fmaf(uv.y, wb.x, ha[m]);
                ca[m] = fmaf(uv.y, wb.y, ca[m]);
            }
        }
        __syncthreads();           // all z reads done before overwriting h-region
#pragma unroll
        for (int m = 0; m < 8; m++) {
            h[m] = ha[m]; c[m] = ca[m];
            u[rb + m][INDIM + t] = ha[m];
        }
    }

    const float4 bg = ((const float4*)(g_scratch + OFF_BG4))[t];
    const int ym = tid >> 5;       // y-GEMM row (warp == row)
    const int jj = tid & 31;
    const float* wo = g_scratch + OFF_WO3;
    const float b0 = g_scratch[OFF_BO3 + jj];
    const float b1 = g_scratch[OFF_BO3 + jj + 32];
    const float b2 = g_scratch[OFF_BO3 + jj + 64];

    for (int step = 0; step < 8; step++) {
        __syncthreads();           // h (and x) writes visible to all

        // ---- gates GEMM: [i|f|g|o] = u @ Wg + bias ----
        float ai[8], af[8], ag[8], ao[8];
#pragma unroll
        for (int m = 0; m < 8; m++) { ai[m] = bg.x; af[m] = bg.y; ag[m] = bg.z; ao[m] = bg.w; }
        const float4* wg = (const float4*)(g_scratch + OFF_WG4);
#pragma unroll 2
        for (int k = 0; k < KG; k += 2) {
            float4 wa = wg[k * 256 + t];
            float4 wb = wg[(k + 1) * 256 + t];
#pragma unroll
            for (int m = 0; m < 8; m++) {
                float2 uv = *(const float2*)&u[rb + m][k];
                ai[m] = fmaf(uv.x, wa.x, ai[m]);
                af[m] = fmaf(uv.x, wa.y, af[m]);
                ag[m] = fmaf(uv.x, wa.z, ag[m]);
                ao[m] = fmaf(uv.x, wa.w, ao[m]);
                ai[m] = fmaf(uv.y, wb.x, ai[m]);
                af[m] = fmaf(uv.y, wb.y, af[m]);
                ag[m] = fmaf(uv.y, wb.z, ag[m]);
                ao[m] = fmaf(uv.y, wb.w, ao[m]);
            }
        }

        // ---- elementwise LSTM cell (thread t owns hidden unit t) ----
#pragma unroll
        for (int m = 0; m < 8; m++) {
            float iv = sigf(ai[m]);
            float fv = sigf(af[m]);
            float gv = tanhfast(ag[m]);
            float ov = sigf(ao[m]);
            c[m] = fmaf(fv, c[m], iv * gv);
            h[m] = ov * tanhfast(c[m]);
        }
        __syncthreads();           // all u reads done before h overwrite
#pragma unroll
        for (int m = 0; m < 8; m++) u[rb + m][INDIM + t] = h[m];
        __syncthreads();

        // ---- y-GEMM: y = sigmoid(h @ Wo^T + bo); feed back as next x ----
        float y0 = b0, y1 = b1, y2 = b2;
#pragma unroll 4
        for (int n = 0; n < HIDDEN; n++) {
            float hv = u[ym][INDIM + n];
            const float* wr = wo + n * 96;
            y0 = fmaf(hv, wr[jj],      y0);
            y1 = fmaf(hv, wr[jj + 32], y1);
            y2 = fmaf(hv, wr[jj + 64], y2);
        }
        y0 = sigf(y0); y1 = sigf(y1); y2 = sigf(y2);
        u[ym][jj]      = y0;
        u[ym][jj + 32] = y1;
        size_t ob = ((size_t)(m0 + ym) * 8 + step) * 72;
        out[ob + jj]      = y0;
        out[ob + jj + 32] = y1;
        if (jj + 64 < INDIM) {
            u[ym][jj + 64] = y2;
            out[ob + jj + 64] = y2;
        }
    }
}

extern "C" void kernel_launch(void* const* d_in, const int* in_sizes, int n_in,
                              void* d_out, int out_size) {
    const float* z    = (const float*)d_in[0];
    const float* W_ih = (const float*)d_in[1];
    const float* W_hh = (const float*)d_in[2];
    const float* b_ih = (const float*)d_in[3];
    const float* b_hh = (const float*)d_in[4];
    const float* Wh   = (const float*)d_in[5];
    const float* bh   = (const float*)d_in[6];
    const float* Wc   = (const float*)d_in[7];
    const float* bc   = (const float*)d_in[8];
    const float* Wo   = (const float*)d_in[9];
    const float* bo   = (const float*)d_in[10];
    float* out = (float*)d_out;

    int B = in_sizes[0] / HIDDEN;   // z is (1, B, 256)

    prep_kernel<<<256, 256>>>(W_ih, W_hh, b_ih, b_hh, Wh, Wc, Wo, bo);
    lstm_main<<<B / MTILE, NTH>>>(z, bh, bc, out);
}

// round 10
// speedup vs baseline: 1.0392x; 1.0392x over previous
#include <cuda_runtime.h>

typedef unsigned long long ull;

#define HIDDEN 256
#define INDIM  72
#define KG     328            // 72 (x) + 256 (h)
#define MTILE  16
#define NTH    512
#define USTR   336            // padded row stride (float2 units)

// scratch offsets (floats)
#define OFF_WG4 0                          // [328][256][4] gate weights (i,f,g,o), k-major
#define OFF_BG4 (KG*1024)                  // [256][4] fused gate bias
#define OFF_WI2 (OFF_BG4 + 1024)           // [256][256][2] init weights (Wh,Wc), k-major
#define OFF_WO2 (OFF_WI2 + HIDDEN*512)     // [256][36][2] output weight col-pairs, k-major
#define NSCR    (OFF_WO2 + HIDDEN*72)

__device__ __align__(16) float g_scratch[NSCR];

// ---------------- packed fp32x2 helpers ----------------
__device__ __forceinline__ ull pk2(float x, float y) {
    ull r; asm("mov.b64 %0,{%1,%2};" : "=l"(r) : "f"(x), "f"(y)); return r;
}
__device__ __forceinline__ void upk2(ull v, float& x, float& y) {
    asm("mov.b64 {%0,%1},%2;" : "=f"(x), "=f"(y) : "l"(v));
}
__device__ __forceinline__ ull ffma2(ull a, ull b, ull c) {
    ull d; asm("fma.rn.f32x2 %0,%1,%2,%3;" : "=l"(d) : "l"(a), "l"(b), "l"(c)); return d;
}

__global__ void prep_kernel(const float* __restrict__ W_ih, const float* __restrict__ W_hh,
                            const float* __restrict__ b_ih, const float* __restrict__ b_hh,
                            const float* __restrict__ Wh,   const float* __restrict__ Wc,
                            const float* __restrict__ Wo) {
    for (int i = blockIdx.x * blockDim.x + threadIdx.x; i < NSCR;
         i += gridDim.x * blockDim.x) {
        float v;
        if (i < OFF_BG4) {
            int g = i & 3, t = (i >> 2) & 255, k = i >> 10;
            int n = g * 256 + t;
            v = (k < INDIM) ? W_ih[n * INDIM + k] : W_hh[n * HIDDEN + (k - INDIM)];
        } else if (i < OFF_WI2) {
            int j = i - OFF_BG4;
            int n = (j & 3) * 256 + (j >> 2);
            v = b_ih[n] + b_hh[n];
        } else if (i < OFF_WO2) {
            int j = i - OFF_WI2;
            int e = j & 1, t = (j >> 1) & 255, k = j >> 9;
            v = e ? Wc[t * HIDDEN + k] : Wh[t * HIDDEN + k];
        } else {
            int j = i - OFF_WO2;
            int e = j & 1, p = (j >> 1) % 36, k = j / 72;
            v = Wo[(2 * p + e) * HIDDEN + k];
        }
        g_scratch[i] = v;
    }
}

__device__ __forceinline__ float sigf(float x) {
    return __fdividef(1.0f, 1.0f + __expf(-x));
}
__device__ __forceinline__ float tanhfast(float x) {
    return fmaf(2.0f, sigf(2.0f * x), -1.0f);
}

__global__ void __launch_bounds__(NTH, 1)
lstm_main(const float* __restrict__ z, const float* __restrict__ bh,
          const float* __restrict__ bc, const float* __restrict__ bo,
          float* __restrict__ out) {
    __shared__ __align__(16) float2 u2[MTILE][USTR];  // [m][k] = (v,v): k<72 x, 72..327 h
    const int tid = threadIdx.x;
    const int m0 = blockIdx.x * MTILE;

    // ---- load z tile duplicated into h-region; zero x-region ----
    for (int i = tid; i < MTILE * HIDDEN; i += NTH) {
        int m = i >> 8, k = i & 255;
        float v = z[(size_t)(m0 + m) * HIDDEN + k];
        u2[m][INDIM + k] = make_float2(v, v);
    }
    for (int i = tid; i < MTILE * INDIM; i += NTH)
        u2[i / INDIM][i % INDIM] = make_float2(0.0f, 0.0f);
    __syncthreads();

    const int t  = tid & 255;        // hidden / gate column owner
    const int rb = (tid >> 8) * 8;   // row base: 0 or 8

    // ---- init GEMM: packed (h,c) accumulators ----
    float h[8], c[8];
    {
        ull ahc[8];
        const ull bhc = pk2(bh[t], bc[t]);
#pragma unroll
        for (int m = 0; m < 8; m++) ahc[m] = bhc;
        const ull* wi = (const ull*)(g_scratch + OFF_WI2);
        ull w0 = wi[t], w1 = wi[256 + t];
#pragma unroll 2
        for (int k = 0; k < HIDDEN; k += 2) {
            ull nw0 = wi[(k + 2) * 256 + t];   // harmless tail over-read inside g_scratch
            ull nw1 = wi[(k + 3) * 256 + t];
#pragma unroll
            for (int m = 0; m < 8; m++) {
                ulonglong2 ud = *(const ulonglong2*)&u2[rb + m][INDIM + k];
                ahc[m] = ffma2(ud.x, w0, ahc[m]);
                ahc[m] = ffma2(ud.y, w1, ahc[m]);
            }
            w0 = nw0; w1 = nw1;
        }
        __syncthreads();           // all z reads done before overwriting h-region
#pragma unroll
        for (int m = 0; m < 8; m++) {
            upk2(ahc[m], h[m], c[m]);
            u2[rb + m][INDIM + t] = make_float2(h[m], h[m]);
        }
    }

    // gate bias pairs
    ull bgl, bgh;
    {
        float4 bg = ((const float4*)(g_scratch + OFF_BG4))[t];
        bgl = pk2(bg.x, bg.y);
        bgh = pk2(bg.z, bg.w);
    }
    // y-GEMM mapping: warp = row; lane jj owns cols (2jj,2jj+1); lanes 0..3 also (64+2jj,65+2jj)
    const int ym = tid >> 5;
    const int jj = tid & 31;
    const int p2 = 32 + (jj & 3);
    const float2 bp0 = ((const float2*)bo)[jj];
    const float2 bp1 = ((const float2*)bo)[p2];

    for (int step = 0; step < 8; step++) {
        __syncthreads();           // x and h writes visible

        // ---- gates GEMM: packed (i,f) and (g,o) accumulators ----
        ull aif[8], ago[8];
#pragma unroll
        for (int m = 0; m < 8; m++) { aif[m] = bgl; ago[m] = bgh; }
        const ulonglong2* wg = (const ulonglong2*)(g_scratch + OFF_WG4);
        ulonglong2 w0 = wg[t], w1 = wg[256 + t];
#pragma unroll 2
        for (int k = 0; k < KG; k += 2) {
            ulonglong2 nw0 = wg[(k + 2) * 256 + t];  // tail over-read stays in g_scratch
            ulonglong2 nw1 = wg[(k + 3) * 256 + t];
#pragma unroll
            for (int m = 0; m < 8; m++) {
                ulonglong2 ud = *(const ulonglong2*)&u2[rb + m][k];
                aif[m] = ffma2(ud.x, w0.x, aif[m]);
                ago[m] = ffma2(ud.x, w0.y, ago[m]);
                aif[m] = ffma2(ud.y, w1.x, aif[m]);
                ago[m] = ffma2(ud.y, w1.y, ago[m]);
            }
            w0 = nw0; w1 = nw1;
        }

        // ---- elementwise LSTM cell ----
#pragma unroll
        for (int m = 0; m < 8; m++) {
            float ai, af, ag, ao;
            upk2(aif[m], ai, af);
            upk2(ago[m], ag, ao);
            float iv = sigf(ai);
            float fv = sigf(af);
            float gv = tanhfast(ag);
            float ov = sigf(ao);
            c[m] = fmaf(fv, c[m], iv * gv);
            h[m] = ov * tanhfast(c[m]);
        }
        __syncthreads();           // all u reads done before h overwrite
#pragma unroll
        for (int m = 0; m < 8; m++)
            u2[rb + m][INDIM + t] = make_float2(h[m], h[m]);
        __syncthreads();

        // ---- y-GEMM: y = sigmoid(h @ Wo^T + bo), packed col-pairs ----
        ull ya = pk2(bp0.x, bp0.y);
        ull yb = pk2(bp1.x, bp1.y);
        const ull* wo = (const ull*)(g_scratch + OFF_WO2);
#pragma unroll 4
        for (int k = 0; k < HIDDEN; k += 2) {
            ulonglong2 hd = *(const ulonglong2*)&u2[ym][INDIM + k];
            ya = ffma2(hd.x, wo[k * 36 + jj], ya);
            yb = ffma2(hd.x, wo[k * 36 + p2], yb);
            ya = ffma2(hd.y, wo[(k + 1) * 36 + jj], ya);
            yb = ffma2(hd.y, wo[(k + 1) * 36 + p2], yb);
        }
        float y0, y1, y2, y3;
        upk2(ya, y0, y1);
        upk2(yb, y2, y3);
        y0 = sigf(y0); y1 = sigf(y1); y2 = sigf(y2); y3 = sigf(y3);

        size_t ob = ((size_t)(m0 + ym) * 8 + step) * 72;
        u2[ym][2 * jj]     = make_float2(y0, y0);
        u2[ym][2 * jj + 1] = make_float2(y1, y1);
        *(float2*)&out[ob + 2 * jj] = make_float2(y0, y1);
        if (jj < 4) {
            u2[ym][64 + 2 * jj] = make_float2(y2, y2);
            u2[ym][65 + 2 * jj] = make_float2(y3, y3);
            *(float2*)&out[ob + 64 + 2 * jj] = make_float2(y2, y3);
        }
    }
}

extern "C" void kernel_launch(void* const* d_in, const int* in_sizes, int n_in,
                              void* d_out, int out_size) {
    const float* z    = (const float*)d_in[0];
    const float* W_ih = (const float*)d_in[1];
    const float* W_hh = (const float*)d_in[2];
    const float* b_ih = (const float*)d_in[3];
    const float* b_hh = (const float*)d_in[4];
    const float* Wh   = (const float*)d_in[5];
    const float* bh   = (const float*)d_in[6];
    const float* Wc   = (const float*)d_in[7];
    const float* bc   = (const float*)d_in[8];
    const float* Wo   = (const float*)d_in[9];
    const float* bo   = (const float*)d_in[10];
    float* out = (float*)d_out;

    int B = in_sizes[0] / HIDDEN;   // z is (1, B, 256)

    prep_kernel<<<256, 256>>>(W_ih, W_hh, b_ih, b_hh, Wh, Wc, Wo);
    lstm_main<<<B / MTILE, NTH>>>(z, bh, bc, bo, out);
}

// round 11
// speedup vs baseline: 1.2944x; 1.2456x over previous
#include <cuda_runtime.h>

typedef unsigned long long ull;

#define HIDDEN 256
#define INDIM  72
#define MT     16
#define NT     512
#define KS     41              // ceil(328/8): ksteps 0..8 = x, 9..40 = h

// ---------------- scratch offsets (floats) ----------------
#define OFF_WB  0                          // [128 nt][41 ks][32 lane]{b0,b1} tf32 B-frags
#define SZ_WB   (128*41*64)
#define OFF_BF  (OFF_WB + SZ_WB)           // [128 nt][32 lane]{c0,c1} bias frag pairs
#define SZ_BF   (128*64)
#define OFF_WI2 (OFF_BF + SZ_BF)           // [256 k][256 t]{Wh,Wc} init weights, k-major
#define SZ_WI2  (256*512)
#define OFF_WO2 (OFF_WI2 + SZ_WI2)         // [256 k][36 p]{2} output weight col-pairs
#define SZ_WO2  (256*72)
#define NSCR    (OFF_WO2 + SZ_WO2)

__device__ __align__(16) float g_scratch[NSCR];

// ---------------- SMEM layout (floats) ----------------
#define UA_FLOATS  (KS*16*8)               // 5248 : A tiles [ks][row][colp] (tf32 bits)
#define HD_STRIDE  260                     // float2 per row
#define HD_FLOATS  (16*HD_STRIDE*2)        // 8320 : (h,h) dup pairs
#define PA_STRIDE  1040
#define PA_FLOATS  (16*PA_STRIDE)          // 16640: gate preactivations
#define SMEM_FLOATS (UA_FLOATS + HD_FLOATS + PA_FLOATS)
#define SMEM_BYTES  (SMEM_FLOATS*4)        // 120832

// ---------------- helpers ----------------
__device__ __forceinline__ ull pk2(float x, float y) {
    ull r; asm("mov.b64 %0,{%1,%2};" : "=l"(r) : "f"(x), "f"(y)); return r;
}
__device__ __forceinline__ void upk2(ull v, float& x, float& y) {
    asm("mov.b64 {%0,%1},%2;" : "=f"(x), "=f"(y) : "l"(v));
}
__device__ __forceinline__ ull ffma2(ull a, ull b, ull c) {
    ull d; asm("fma.rn.f32x2 %0,%1,%2,%3;" : "=l"(d) : "l"(a), "l"(b), "l"(c)); return d;
}
__device__ __forceinline__ float tf32f(float x) {
    unsigned u; asm("cvt.rna.tf32.f32 %0,%1;" : "=r"(u) : "f"(x));
    return __uint_as_float(u);
}
__device__ __forceinline__ int permc(int c) { return ((c & 3) << 1) | ((c >> 2) & 1); }

__device__ __forceinline__ void mma4(float C[4], float a0, float a1, float a2, float a3,
                                     float b0, float b1) {
    asm("mma.sync.aligned.m16n8k8.row.col.f32.tf32.tf32.f32 "
        "{%0,%1,%2,%3},{%4,%5,%6,%7},{%8,%9},{%0,%1,%2,%3};"
        : "+f"(C[0]), "+f"(C[1]), "+f"(C[2]), "+f"(C[3])
        : "r"(__float_as_uint(a0)), "r"(__float_as_uint(a1)),
          "r"(__float_as_uint(a2)), "r"(__float_as_uint(a3)),
          "r"(__float_as_uint(b0)), "r"(__float_as_uint(b1)));
}

__device__ __forceinline__ float sigf(float x) {
    return __fdividef(1.0f, 1.0f + __expf(-x));
}
__device__ __forceinline__ float tanhfast(float x) {
    return fmaf(2.0f, sigf(2.0f * x), -1.0f);
}

// ---------------- prep: pack weights ----------------
__global__ void prep_kernel(const float* __restrict__ W_ih, const float* __restrict__ W_hh,
                            const float* __restrict__ b_ih, const float* __restrict__ b_hh,
                            const float* __restrict__ Wh,   const float* __restrict__ Wc,
                            const float* __restrict__ Wo) {
    for (int i = blockIdx.x * blockDim.x + threadIdx.x; i < NSCR;
         i += gridDim.x * blockDim.x) {
        float v;
        if (i < OFF_BF) {                       // tf32 B-fragments of gate weights
            int e = i & 1, p = i >> 1;
            int lane = p & 31, q = p >> 5;
            int ks = q % KS, nt = q / KS;
            int gid = lane >> 2, tig = lane & 3;
            int n = nt * 8 + gid;               // gate column (torch order)
            int k = ks * 8 + tig + 4 * e;
            float w = (k < INDIM) ? W_ih[n * INDIM + k] : W_hh[n * HIDDEN + (k - INDIM)];
            v = tf32f(w);
        } else if (i < OFF_WI2) {               // bias in C-fragment pair order
            int j = i - OFF_BF;
            int e = j & 1, p = j >> 1;
            int lane = p & 31, nt = p >> 5;
            int tig = lane & 3;
            int n = nt * 8 + 2 * tig + e;
            v = b_ih[n] + b_hh[n];
        } else if (i < OFF_WO2) {               // init weights (Wh,Wc) k-major fp32
            int j = i - OFF_WI2;
            int e = j & 1, t = (j >> 1) & 255, k = j >> 9;
            v = e ? Wc[t * HIDDEN + k] : Wh[t * HIDDEN + k];
        } else {                                // output weight col-pairs fp32
            int j = i - OFF_WO2;
            int e = j & 1, pp = (j >> 1) % 36, k = j / 72;
            v = Wo[(2 * pp + e) * HIDDEN + k];
        }
        g_scratch[i] = v;
    }
}

// ---------------- fused LSTM main ----------------
__global__ void __launch_bounds__(NT, 1)
lstm_main(const float* __restrict__ z, const float* __restrict__ bh,
          const float* __restrict__ bc, const float* __restrict__ bo,
          float* __restrict__ out) {
    extern __shared__ __align__(16) float sm[];
    float*  uA = sm;                                     // tf32 A tiles
    float2* hd = (float2*)(sm + UA_FLOATS);              // (h,h) dup
    float*  pa = sm + UA_FLOATS + HD_FLOATS;             // gate preacts

    const int tid  = threadIdx.x;
    const int m0   = blockIdx.x * MT;
    const int lane = tid & 31;
    const int w    = tid >> 5;
    const int gid  = lane >> 2;
    const int tig  = lane & 3;
    const int t    = tid & 255;
    const int rb   = (tid >> 8) * 8;

    // ---- z dup into hd; zero uA x-region ----
    for (int i = tid; i < MT * HIDDEN; i += NT) {
        int m = i >> 8, k = i & 255;
        float v = z[(size_t)(m0 + m) * HIDDEN + k];
        hd[m * HD_STRIDE + k] = make_float2(v, v);
    }
    for (int i = tid; i < 9 * 128; i += NT) uA[i] = 0.0f;   // ks 0..8 = x = 0
    __syncthreads();

    // ---- init GEMM (fp32 FFMA2): h = z@Wh^T+bh, c = z@Wc^T+bc ----
    float h[8], c[8];
    {
        ull ahc[8];
        const ull bi = pk2(bh[t], bc[t]);
#pragma unroll
        for (int m = 0; m < 8; m++) ahc[m] = bi;
        const ull* wi = (const ull*)(g_scratch + OFF_WI2);
        ull w0 = wi[t], w1 = wi[256 + t];
#pragma unroll 2
        for (int k = 0; k < HIDDEN; k += 2) {
            ull nw0 = wi[(k + 2) * 256 + t];    // tail over-read stays in g_scratch
            ull nw1 = wi[(k + 3) * 256 + t];
#pragma unroll
            for (int m = 0; m < 8; m++) {
                ulonglong2 ud = *(const ulonglong2*)&hd[(rb + m) * HD_STRIDE + k];
                ahc[m] = ffma2(ud.x, w0, ahc[m]);
                ahc[m] = ffma2(ud.y, w1, ahc[m]);
            }
            w0 = nw0; w1 = nw1;
        }
        __syncthreads();                        // all z reads done
        const int kh = INDIM + t, ksh = kh >> 3, cph = permc(kh & 7);
#pragma unroll
        for (int m = 0; m < 8; m++) {
            upk2(ahc[m], h[m], c[m]);
            hd[(rb + m) * HD_STRIDE + t] = make_float2(h[m], h[m]);
            uA[(ksh * 16 + rb + m) * 8 + cph] = tf32f(h[m]);
        }
    }

    // ---- persistent y-GEMM mapping ----
    const int ym = tid >> 5;
    const int jj = tid & 31;
    const int p2 = 32 + (jj & 3);
    const float2 bp0 = ((const float2*)bo)[jj];
    const float2 bp1 = ((const float2*)bo)[p2];

    const float2* wbp = (const float2*)g_scratch + (size_t)w * 8 * KS * 32 + lane;
    const float2* bfp = (const float2*)(g_scratch + OFF_BF) + w * 8 * 32 + lane;
    const int kh = INDIM + t, ksh = kh >> 3, cph = permc(kh & 7);

    for (int step = 0; step < 8; step++) {
        __syncthreads();                        // h / x writes visible

        // ---- gates GEMM on tensor cores ----
        float C[8][4];
#pragma unroll
        for (int j = 0; j < 8; j++) {
            float2 bb = bfp[j * 32];
            C[j][0] = bb.x; C[j][1] = bb.y; C[j][2] = bb.x; C[j][3] = bb.y;
        }
        float2 bq0[8], bq1[8];
#pragma unroll
        for (int j = 0; j < 8; j++) {
            bq0[j] = wbp[(j * KS + 0) * 32];
            bq1[j] = wbp[(j * KS + 1) * 32];
        }
        const float* ua0 = uA + gid * 8 + 2 * tig;
        const float* ua1 = uA + (gid + 8) * 8 + 2 * tig;
        for (int ks = 0; ks < KS; ks += 2) {
            float2 fa = *(const float2*)(ua0 + ks * 128);
            float2 fb = *(const float2*)(ua1 + ks * 128);
#pragma unroll
            for (int j = 0; j < 8; j++) {
                float2 bb = bq0[j];
                if (ks + 2 < KS) bq0[j] = wbp[(j * KS + ks + 2) * 32];
                mma4(C[j], fa.x, fb.x, fa.y, fb.y, bb.x, bb.y);
            }
            if (ks + 1 < KS) {
                fa = *(const float2*)(ua0 + (ks + 1) * 128);
                fb = *(const float2*)(ua1 + (ks + 1) * 128);
#pragma unroll
                for (int j = 0; j < 8; j++) {
                    float2 bb = bq1[j];
                    if (ks + 3 < KS) bq1[j] = wbp[(j * KS + ks + 3) * 32];
                    mma4(C[j], fa.x, fb.x, fa.y, fb.y, bb.x, bb.y);
                }
            }
        }
        // epilogue: preacts -> SMEM
        {
            const int nb = w * 64 + 2 * tig;
#pragma unroll
            for (int j = 0; j < 8; j++) {
                *(float2*)&pa[gid * PA_STRIDE + nb + j * 8]       = make_float2(C[j][0], C[j][1]);
                *(float2*)&pa[(gid + 8) * PA_STRIDE + nb + j * 8] = make_float2(C[j][2], C[j][3]);
            }
        }
        __syncthreads();

        // ---- elementwise LSTM cell (thread t owns unit t, 8 rows) ----
#pragma unroll
        for (int m = 0; m < 8; m++) {
            const float* pr = pa + (rb + m) * PA_STRIDE + t;
            float iv = sigf(pr[0]);
            float fv = sigf(pr[256]);
            float gv = tanhfast(pr[512]);
            float ov = sigf(pr[768]);
            c[m] = fmaf(fv, c[m], iv * gv);
            h[m] = ov * tanhfast(c[m]);
        }
#pragma unroll
        for (int m = 0; m < 8; m++) {
            hd[(rb + m) * HD_STRIDE + t] = make_float2(h[m], h[m]);
            uA[(ksh * 16 + rb + m) * 8 + cph] = tf32f(h[m]);
        }
        __syncthreads();

        // ---- y-GEMM (fp32 FFMA2): y = sigmoid(h @ Wo^T + bo) ----
        ull ya = pk2(bp0.x, bp0.y);
        ull yb = pk2(bp1.x, bp1.y);
        const ull* wo = (const ull*)(g_scratch + OFF_WO2);
#pragma unroll 4
        for (int k = 0; k < HIDDEN; k += 2) {
            ulonglong2 hv = *(const ulonglong2*)&hd[ym * HD_STRIDE + k];
            ya = ffma2(hv.x, wo[k * 36 + jj], ya);
            yb = ffma2(hv.x, wo[k * 36 + p2], yb);
            ya = ffma2(hv.y, wo[(k + 1) * 36 + jj], ya);
            yb = ffma2(hv.y, wo[(k + 1) * 36 + p2], yb);
        }
        float y0, y1, y2, y3;
        upk2(ya, y0, y1); upk2(yb, y2, y3);
        y0 = sigf(y0); y1 = sigf(y1); y2 = sigf(y2); y3 = sigf(y3);

        size_t ob = ((size_t)(m0 + ym) * 8 + step) * 72;
        *(float2*)&out[ob + 2 * jj] = make_float2(y0, y1);
        const int j0 = 2 * jj;
        uA[((j0 >> 3) * 16 + ym) * 8 + permc(j0 & 7)]             = tf32f(y0);
        uA[(((j0 + 1) >> 3) * 16 + ym) * 8 + permc((j0 + 1) & 7)] = tf32f(y1);
        if (jj < 4) {
            *(float2*)&out[ob + 64 + 2 * jj] = make_float2(y2, y3);
            const int j2 = 64 + 2 * jj;
            uA[((j2 >> 3) * 16 + ym) * 8 + permc(j2 & 7)]             = tf32f(y2);
            uA[(((j2 + 1) >> 3) * 16 + ym) * 8 + permc((j2 + 1) & 7)] = tf32f(y3);
        }
    }
}

extern "C" void kernel_launch(void* const* d_in, const int* in_sizes, int n_in,
                              void* d_out, int out_size) {
    const float* z    = (const float*)d_in[0];
    const float* W_ih = (const float*)d_in[1];
    const float* W_hh = (const float*)d_in[2];
    const float* b_ih = (const float*)d_in[3];
    const float* b_hh = (const float*)d_in[4];
    const float* Wh   = (const float*)d_in[5];
    const float* bh   = (const float*)d_in[6];
    const float* Wc   = (const float*)d_in[7];
    const float* bc   = (const float*)d_in[8];
    const float* Wo   = (const float*)d_in[9];
    const float* bo   = (const float*)d_in[10];
    float* out = (float*)d_out;

    int B = in_sizes[0] / HIDDEN;   // z is (1, B, 256)

    cudaFuncSetAttribute(lstm_main, cudaFuncAttributeMaxDynamicSharedMemorySize, SMEM_BYTES);
    prep_kernel<<<256, 256>>>(W_ih, W_hh, b_ih, b_hh, Wh, Wc, Wo);
    lstm_main<<<B / MT, NT, SMEM_BYTES>>>(z, bh, bc, bo, out);
}

// round 12
// speedup vs baseline: 7.6053x; 5.8755x over previous
#include <cuda_runtime.h>
#include <cuda_fp16.h>

typedef unsigned int u32;
typedef unsigned long long ull;

#define HIDDEN 256
#define INDIM  72
#define MT     16
#define NT     512

// ---------------- packed weight fragment arrays ----------------
// gates: [nt 0..127][ks2 0..10][lane 0..31] x 8 halfs (two k16-steps per uint4)
__device__ __align__(16) __half g_wb[128 * 11 * 32 * 8];
// gates bias C-frags: [nt][lane] float2
__device__ __align__(16) float  g_bf[128 * 32 * 2];
// init:  [nt 0..63][ks 0..15][lane] x 4 halfs
__device__ __align__(16) __half g_wi[64 * 16 * 32 * 4];
// y:     [nt 0..8][ksy 0..16][lane] x 4 halfs (zero outside h-range)
__device__ __align__(16) __half g_wy[9 * 17 * 32 * 4];
// init bias concat bh|bc
__device__ __align__(16) float  g_bi[512];

// ---------------- SMEM layout ----------------
#define UA_U32    (21 * 16 * 8)            // 2688 half2 units
#define UA_BYTES  (UA_U32 * 4)             // 10752
#define PA_STRIDE 1042                     // floats per row (bank-spread)
#define PA_BYTES  (16 * PA_STRIDE * 4)     // 66688
#define CS_BYTES  (16 * 256 * 4)           // 16384
#define SMEM_BYTES (UA_BYTES + PA_BYTES + CS_BYTES)   // 93824

__device__ __forceinline__ int slotof(int cp) { return ((cp & 3) << 1) | (cp >> 2); }

__device__ __forceinline__ void hmma(float C[4], u32 a0, u32 a1, u32 a2, u32 a3,
                                     u32 b0, u32 b1) {
    asm("mma.sync.aligned.m16n8k16.row.col.f32.f16.f16.f32 "
        "{%0,%1,%2,%3},{%4,%5,%6,%7},{%8,%9},{%0,%1,%2,%3};"
        : "+f"(C[0]), "+f"(C[1]), "+f"(C[2]), "+f"(C[3])
        : "r"(a0), "r"(a1), "r"(a2), "r"(a3), "r"(b0), "r"(b1));
}

__device__ __forceinline__ float tanha(float x) {
    float r; asm("tanh.approx.f32 %0,%1;" : "=f"(r) : "f"(x)); return r;
}
__device__ __forceinline__ float siga(float x) {
    return fmaf(0.5f, tanha(0.5f * x), 0.5f);
}

// ---------------- prep: pack all weights as fp16 mma fragments ----------------
__global__ void prep_kernel(const float* __restrict__ W_ih, const float* __restrict__ W_hh,
                            const float* __restrict__ b_ih, const float* __restrict__ b_hh,
                            const float* __restrict__ Wh,   const float* __restrict__ Wc,
                            const float* __restrict__ Wo,   const float* __restrict__ bh,
                            const float* __restrict__ bc) {
    const int tid = blockIdx.x * blockDim.x + threadIdx.x;
    const int stride = gridDim.x * blockDim.x;

    for (int i = tid; i < 128 * 11 * 32 * 8; i += stride) {   // gates B frags
        int e = i & 7, lane = (i >> 3) & 31, r = i >> 8;
        int ks2 = r % 11, nt = r / 11;
        int gid = lane >> 2, tig = lane & 3;
        int ks = 2 * ks2 + (e >> 2);
        int k = ks * 16 + 2 * tig + (e & 1) + 8 * ((e >> 1) & 1);
        int n = nt * 8 + gid;
        float v = 0.0f;
        if (k < 328) v = (k < INDIM) ? W_ih[n * INDIM + k] : W_hh[n * HIDDEN + (k - INDIM)];
        g_wb[i] = __float2half(v);
    }
    for (int i = tid; i < 128 * 64; i += stride) {            // gates bias frags
        int e = i & 1, lane = (i >> 1) & 31, nt = i >> 6;
        int n = nt * 8 + 2 * (lane & 3) + e;
        g_bf[i] = b_ih[n] + b_hh[n];
    }
    for (int i = tid; i < 64 * 16 * 32 * 4; i += stride) {    // init B frags
        int e = i & 3, lane = (i >> 2) & 31, r = i >> 7;
        int ks = r & 15, nt = r >> 4;
        int gid = lane >> 2, tig = lane & 3;
        int k = ks * 16 + 2 * tig + (e & 1) + 8 * (e >> 1);
        int n = nt * 8 + gid;
        float v = (n < HIDDEN) ? Wh[n * HIDDEN + k] : Wc[(n - HIDDEN) * HIDDEN + k];
        g_wi[i] = __float2half(v);
    }
    for (int i = tid; i < 9 * 17 * 32 * 4; i += stride) {     // y B frags
        int e = i & 3, lane = (i >> 2) & 31, r = i >> 7;
        int ksy = r % 17, nt = r / 17;
        int gid = lane >> 2, tig = lane & 3;
        int ku = (ksy + 4) * 16 + 2 * tig + (e & 1) + 8 * (e >> 1);
        int kw = ku - INDIM;
        int n = nt * 8 + gid;
        float v = (kw >= 0 && kw < HIDDEN) ? Wo[n * HIDDEN + kw] : 0.0f;
        g_wy[i] = __float2half(v);
    }
    for (int i = tid; i < 512; i += stride)
        g_bi[i] = (i < HIDDEN) ? bh[i] : bc[i - HIDDEN];
}

// ---------------- fused LSTM main ----------------
__global__ void __launch_bounds__(NT, 1)
lstm_main(const float* __restrict__ z, const float* __restrict__ bo,
          float* __restrict__ out) {
    extern __shared__ __align__(16) char sm[];
    u32*   uaw = (u32*)sm;                           // activation half2 units [ks][row][slot]
    float* pa  = (float*)(sm + UA_BYTES);            // gate preacts (also zA scratch at init)
    float* cs  = (float*)(sm + UA_BYTES + PA_BYTES); // c init roundtrip
    u32*   zaw = (u32*)pa;

    const int tid  = threadIdx.x;
    const int m0   = blockIdx.x * MT;
    const int lane = tid & 31;
    const int w    = tid >> 5;
    const int gid  = lane >> 2;
    const int tig  = lane & 3;
    const int t    = tid & 255;
    const int rb   = (tid >> 8) * 8;

    // ---- zero uA; load z -> zA as fp16 in A-frag layout ----
    for (int i = tid; i < UA_U32; i += NT) uaw[i] = 0u;
    for (int ii = tid; ii < MT * 128; ii += NT) {
        int m = ii >> 7, k2 = ii & 127;
        float2 zv = *(const float2*)&z[(size_t)(m0 + m) * HIDDEN + 2 * k2];
        __half2 hv = __floats2half2_rn(zv.x, zv.y);
        int ks = k2 >> 3, sl = slotof(k2 & 7);
        zaw[(ks * 16 + m) * 8 + sl] = *reinterpret_cast<u32*>(&hv);
    }
    __syncthreads();

    // ---- init GEMM on tensor cores: [h|c] = z @ [Wh|Wc]^T + [bh|bc] ----
    {
        float C[4][4];
#pragma unroll
        for (int j = 0; j < 4; j++) {
            float2 bb = *(const float2*)&g_bi[(w * 4 + j) * 8 + 2 * tig];
            C[j][0] = bb.x; C[j][1] = bb.y; C[j][2] = bb.x; C[j][3] = bb.y;
        }
        const uint2* wip = (const uint2*)g_wi + (w * 4) * 16 * 32 + lane;
#pragma unroll
        for (int ks = 0; ks < 16; ks++) {
            uint2 fa = *(const uint2*)&zaw[(ks * 16 + gid) * 8 + 2 * tig];
            uint2 fb = *(const uint2*)&zaw[(ks * 16 + gid + 8) * 8 + 2 * tig];
#pragma unroll
            for (int j = 0; j < 4; j++) {
                uint2 wf = wip[(j * 16 + ks) * 32];
                hmma(C[j], fa.x, fb.x, fa.y, fb.y, wf.x, wf.y);
            }
        }
        // epilogue: h -> uA (fp16), c -> cs (fp32)
#pragma unroll
        for (int j = 0; j < 4; j++) {
            int n0 = (w * 4 + j) * 8 + 2 * tig;
            if (n0 < HIDDEN) {
                int kt = INDIM + n0;                        // even
                int unit = ((kt >> 4) * 16) * 8 + slotof((kt & 15) >> 1);
                __half2 ha = __floats2half2_rn(C[j][0], C[j][1]);
                __half2 hb = __floats2half2_rn(C[j][2], C[j][3]);
                uaw[unit + gid * 8]       = *reinterpret_cast<u32*>(&ha);
                uaw[unit + (gid + 8) * 8] = *reinterpret_cast<u32*>(&hb);
            } else {
                int nc = n0 - HIDDEN;
                *(float2*)&cs[gid * 256 + nc]       = make_float2(C[j][0], C[j][1]);
                *(float2*)&cs[(gid + 8) * 256 + nc] = make_float2(C[j][2], C[j][3]);
            }
        }
    }
    __syncthreads();

    // ---- pick up c state into owner registers ----
    float c[8];
#pragma unroll
    for (int m = 0; m < 8; m++) c[m] = cs[(rb + m) * 256 + t];

    // precomputed constants for step loop
    const float2* bfp = (const float2*)g_bf + (w * 8) * 32 + lane;
    const uint4*  wbp = (const uint4*)g_wb + (w * 8) * 11 * 32 + lane;
    u32 ua32 = (u32)__cvta_generic_to_shared(uaw);
    const int kt = INDIM + t;
    const u32 hbase = (((u32)(kt >> 4) * 16 + rb) * 8 + slotof((kt & 15) >> 1)) * 4 + (kt & 1) * 2;

    for (int step = 0; step < 8; step++) {
        __syncthreads();                       // uA (h, x) writes visible

        // ---- gates GEMM (fp16 mma, fully unrolled) ----
        float C[8][4];
#pragma unroll
        for (int j = 0; j < 8; j++) {
            float2 bb = bfp[j * 32];
            C[j][0] = bb.x; C[j][1] = bb.y; C[j][2] = bb.x; C[j][3] = bb.y;
        }
#pragma unroll
        for (int ks2 = 0; ks2 < 11; ks2++) {
            int ks0 = 2 * ks2;
            uint2 fa0 = *(const uint2*)&uaw[(ks0 * 16 + gid) * 8 + 2 * tig];
            uint2 fb0 = *(const uint2*)&uaw[(ks0 * 16 + gid + 8) * 8 + 2 * tig];
            uint2 fa1 = make_uint2(0, 0), fb1 = make_uint2(0, 0);
            if (ks2 < 10) {
                fa1 = *(const uint2*)&uaw[((ks0 + 1) * 16 + gid) * 8 + 2 * tig];
                fb1 = *(const uint2*)&uaw[((ks0 + 1) * 16 + gid + 8) * 8 + 2 * tig];
            }
#pragma unroll
            for (int j = 0; j < 8; j++) {
                uint4 wf = wbp[(j * 11 + ks2) * 32];
                hmma(C[j], fa0.x, fb0.x, fa0.y, fb0.y, wf.x, wf.y);
                if (ks2 < 10)
                    hmma(C[j], fa1.x, fb1.x, fa1.y, fb1.y, wf.z, wf.w);
            }
        }
        // epilogue: preacts -> pa
        {
            const int nb = w * 64 + 2 * tig;
#pragma unroll
            for (int j = 0; j < 8; j++) {
                *(float2*)&pa[gid * PA_STRIDE + nb + j * 8]       = make_float2(C[j][0], C[j][1]);
                *(float2*)&pa[(gid + 8) * PA_STRIDE + nb + j * 8] = make_float2(C[j][2], C[j][3]);
            }
        }
        __syncthreads();

        // ---- elementwise LSTM cell (thread t owns unit t, 8 rows) ----
#pragma unroll
        for (int m = 0; m < 8; m++) {
            const float* pr = pa + (rb + m) * PA_STRIDE + t;
            float iv = siga(pr[0]);
            float fv = siga(pr[256]);
            float gv = tanha(pr[512]);
            float ov = siga(pr[768]);
            c[m] = fmaf(fv, c[m], iv * gv);
            float h = ov * tanha(c[m]);
            unsigned short hr = __half_as_ushort(__float2half_rn(h));
            asm volatile("st.shared.u16 [%0], %1;" :: "r"(ua32 + hbase + m * 32), "h"(hr));
        }
        __syncthreads();                       // h writes visible to y-GEMM

        // ---- y-GEMM on tensor cores (warps 0..8): y = sigmoid(h @ Wo^T + bo) ----
        if (w < 9) {
            float Y[4];
            float2 bb = *(const float2*)&bo[w * 8 + 2 * tig];
            Y[0] = bb.x; Y[1] = bb.y; Y[2] = bb.x; Y[3] = bb.y;
            const uint2* wyp = (const uint2*)g_wy + (w * 17) * 32 + lane;
#pragma unroll
            for (int ky = 0; ky < 17; ky++) {
                int ks = ky + 4;
                uint2 fa = *(const uint2*)&uaw[(ks * 16 + gid) * 8 + 2 * tig];
                uint2 fb = *(const uint2*)&uaw[(ks * 16 + gid + 8) * 8 + 2 * tig];
                uint2 wf = wyp[ky * 32];
                hmma(Y, fa.x, fb.x, fa.y, fb.y, wf.x, wf.y);
            }
            float y0 = siga(Y[0]), y1 = siga(Y[1]), y2 = siga(Y[2]), y3 = siga(Y[3]);
            int col = w * 8 + 2 * tig;
            size_t ob0 = ((size_t)(m0 + gid) * 8 + step) * INDIM + col;
            size_t ob1 = ((size_t)(m0 + gid + 8) * 8 + step) * INDIM + col;
            *(float2*)&out[ob0] = make_float2(y0, y1);
            *(float2*)&out[ob1] = make_float2(y2, y3);
            // feedback x into uA (fp16)
            int unit = ((col >> 4) * 16) * 8 + slotof((col & 15) >> 1);
            __half2 xa = __floats2half2_rn(y0, y1);
            __half2 xb = __floats2half2_rn(y2, y3);
            uaw[unit + gid * 8]       = *reinterpret_cast<u32*>(&xa);
            uaw[unit + (gid + 8) * 8] = *reinterpret_cast<u32*>(&xb);
        }
    }
}

extern "C" void kernel_launch(void* const* d_in, const int* in_sizes, int n_in,
                              void* d_out, int out_size) {
    const float* z    = (const float*)d_in[0];
    const float* W_ih = (const float*)d_in[1];
    const float* W_hh = (const float*)d_in[2];
    const float* b_ih = (const float*)d_in[3];
    const float* b_hh = (const float*)d_in[4];
    const float* Wh   = (const float*)d_in[5];
    const float* bh   = (const float*)d_in[6];
    const float* Wc   = (const float*)d_in[7];
    const float* bc   = (const float*)d_in[8];
    const float* Wo   = (const float*)d_in[9];
    const float* bo   = (const float*)d_in[10];
    float* out = (float*)d_out;

    int B = in_sizes[0] / HIDDEN;   // z is (1, B, 256)

    cudaFuncSetAttribute(lstm_main, cudaFuncAttributeMaxDynamicSharedMemorySize, SMEM_BYTES);
    prep_kernel<<<512, 256>>>(W_ih, W_hh, b_ih, b_hh, Wh, Wc, Wo, bh, bc);
    lstm_main<<<B / MT, NT, SMEM_BYTES>>>(z, bo, out);
}

// round 13
// speedup vs baseline: 8.8438x; 1.1629x over previous
#include <cuda_runtime.h>
#include <cuda_fp16.h>

typedef unsigned int u32;

#define HIDDEN 256
#define INDIM  72
#define MT     32
#define NT     512

// ---------------- packed weight fragment arrays ----------------
// gates: [ntg 0..127][ks2 0..10][lane] x 8 halfs. ntg = w*8 + (jj*2+s); s=0:(i,f) tile, s=1:(g,o)
__device__ __align__(16) __half g_wb[128 * 11 * 32 * 8];
// gates bias C-frags, reordered: [ntg][lane] float2
__device__ __align__(16) float  g_bf[128 * 32 * 2];
// init: [T 0..63][ks 0..15][lane] x 4 halfs, (h,c) unit-interleaved columns
__device__ __align__(16) __half g_wi[64 * 16 * 32 * 4];
// init bias frags: [T][lane] float2 = (bh_u, bc_u)
__device__ __align__(16) float  g_bi[64 * 32 * 2];
// y: [nt 0..8][ksy 0..16][lane] x 4 halfs (zero outside h-range)
__device__ __align__(16) __half g_wy[9 * 17 * 32 * 4];

__device__ __forceinline__ int slotof(int cp) { return ((cp & 3) << 1) | (cp >> 2); }

__device__ __forceinline__ void hmma(float C[4], u32 a0, u32 a1, u32 a2, u32 a3,
                                     u32 b0, u32 b1) {
    asm("mma.sync.aligned.m16n8k16.row.col.f32.f16.f16.f32 "
        "{%0,%1,%2,%3},{%4,%5,%6,%7},{%8,%9},{%0,%1,%2,%3};"
        : "+f"(C[0]), "+f"(C[1]), "+f"(C[2]), "+f"(C[3])
        : "r"(a0), "r"(a1), "r"(a2), "r"(a3), "r"(b0), "r"(b1));
}
__device__ __forceinline__ float tanha(float x) {
    float r; asm("tanh.approx.f32 %0,%1;" : "=f"(r) : "f"(x)); return r;
}
__device__ __forceinline__ float siga(float x) {
    return fmaf(0.5f, tanha(0.5f * x), 0.5f);
}

// ---------------- prep: pack weights as fp16 mma fragments ----------------
__global__ void prep_kernel(const float* __restrict__ W_ih, const float* __restrict__ W_hh,
                            const float* __restrict__ b_ih, const float* __restrict__ b_hh,
                            const float* __restrict__ Wh,   const float* __restrict__ Wc,
                            const float* __restrict__ Wo,   const float* __restrict__ bh,
                            const float* __restrict__ bc) {
    const int tid = blockIdx.x * blockDim.x + threadIdx.x;
    const int stride = gridDim.x * blockDim.x;

    // gates B frags (reordered columns)
    for (int i = tid; i < 128 * 11 * 32 * 8; i += stride) {
        int e = i & 7, lane = (i >> 3) & 31, r = i >> 8;
        int ks2 = r % 11, ntg = r / 11;
        int wq = ntg >> 3, q = ntg & 7, jj = q >> 1, s = q & 1;
        int T = wq * 4 + jj;
        int gid = lane >> 2, tig = lane & 3;
        int col = 8 * T + gid;                  // column in the 512-col (pair) matrix
        int u = col >> 1, comp = col & 1;       // unit, which-of-pair
        int g = s ? (comp ? 3 : 2) : (comp ? 1 : 0);   // i,f,g,o torch order
        int n = g * 256 + u;
        int ks = 2 * ks2 + (e >> 2);
        int k = ks * 16 + 2 * tig + (e & 1) + 8 * ((e >> 1) & 1);
        float v = 0.0f;
        if (k < 328) v = (k < INDIM) ? W_ih[n * INDIM + k] : W_hh[n * HIDDEN + (k - INDIM)];
        g_wb[i] = __float2half(v);
    }
    // gates bias frags
    for (int i = tid; i < 128 * 64; i += stride) {
        int e = i & 1, lane = (i >> 1) & 31, ntg = i >> 6;
        int wq = ntg >> 3, q = ntg & 7, jj = q >> 1, s = q & 1;
        int T = wq * 4 + jj;
        int tig = lane & 3;
        int col = 8 * T + 2 * tig + e;
        int u = col >> 1, comp = col & 1;
        int g = s ? (comp ? 3 : 2) : (comp ? 1 : 0);
        int n = g * 256 + u;
        g_bf[i] = b_ih[n] + b_hh[n];
    }
    // init B frags: (h,c) interleaved columns
    for (int i = tid; i < 64 * 16 * 32 * 4; i += stride) {
        int e = i & 3, lane = (i >> 2) & 31, r = i >> 7;
        int ks = r & 15, T = r >> 4;
        int gid = lane >> 2, tig = lane & 3;
        int col = 8 * T + gid;
        int u = col >> 1, comp = col & 1;
        int k = ks * 16 + 2 * tig + (e & 1) + 8 * (e >> 1);
        float v = comp ? Wc[u * HIDDEN + k] : Wh[u * HIDDEN + k];
        g_wi[i] = __float2half(v);
    }
    // init bias frags
    for (int i = tid; i < 64 * 64; i += stride) {
        int e = i & 1, lane = (i >> 1) & 31, T = i >> 6;
        int tig = lane & 3;
        int col = 8 * T + 2 * tig + e;
        int u = col >> 1, comp = col & 1;
        g_bi[i] = comp ? bc[u] : bh[u];
    }
    // y B frags
    for (int i = tid; i < 9 * 17 * 32 * 4; i += stride) {
        int e = i & 3, lane = (i >> 2) & 31, r = i >> 7;
        int ksy = r % 17, nt = r / 17;
        int gid = lane >> 2, tig = lane & 3;
        int ku = (ksy + 4) * 16 + 2 * tig + (e & 1) + 8 * (e >> 1);
        int kw = ku - INDIM;
        int n = nt * 8 + gid;
        float v = (kw >= 0 && kw < HIDDEN) ? Wo[n * HIDDEN + kw] : 0.0f;
        g_wy[i] = __float2half(v);
    }
}

// ---------------- fused LSTM main ----------------
__global__ void __launch_bounds__(NT, 1)
lstm_main(const float* __restrict__ z, const float* __restrict__ bo,
          float* __restrict__ out) {
    __shared__ __align__(16) u32 uaw[21 * MT * 8];   // activations, half2 A-frag layout
    __shared__ __align__(16) u32 zaw[16 * MT * 8];   // z staging (init only)

    const int tid  = threadIdx.x;
    const int m0   = blockIdx.x * MT;
    const int lane = tid & 31;
    const int w    = tid >> 5;
    const int gid  = lane >> 2;
    const int tig  = lane & 3;

    // ---- zero uA; stage z as fp16 A-frags ----
    for (int i = tid; i < 21 * MT * 8; i += NT) uaw[i] = 0u;
    for (int ii = tid; ii < MT * 128; ii += NT) {
        int m = ii >> 7, k2 = ii & 127;
        float2 zv = *(const float2*)&z[(size_t)(m0 + m) * HIDDEN + 2 * k2];
        __half2 hv = __floats2half2_rn(zv.x, zv.y);
        zaw[((k2 >> 3) * MT + m) * 8 + slotof(k2 & 7)] = *reinterpret_cast<u32*>(&hv);
    }
    __syncthreads();

    const u32 ua32 = (u32)__cvta_generic_to_shared(uaw);

    // ---- init GEMM: (h,c) pairs land in owner registers ----
    float c[16];                                  // c[jj*4 + mi*2 + r]
    {
        float Ci[2][4][4];
#pragma unroll
        for (int jj = 0; jj < 4; jj++) {
            float2 bb = *(const float2*)&g_bi[((w * 4 + jj) * 32 + lane) * 2];
#pragma unroll
            for (int mi = 0; mi < 2; mi++) {
                Ci[mi][jj][0] = bb.x; Ci[mi][jj][1] = bb.y;
                Ci[mi][jj][2] = bb.x; Ci[mi][jj][3] = bb.y;
            }
        }
        const uint2* wip = (const uint2*)g_wi + (w * 4) * 16 * 32 + lane;
#pragma unroll
        for (int ks = 0; ks < 16; ks++) {
            uint2 fa0 = *(const uint2*)&zaw[(ks * MT + gid) * 8 + 2 * tig];
            uint2 fb0 = *(const uint2*)&zaw[(ks * MT + gid + 8) * 8 + 2 * tig];
            uint2 fa1 = *(const uint2*)&zaw[(ks * MT + 16 + gid) * 8 + 2 * tig];
            uint2 fb1 = *(const uint2*)&zaw[(ks * MT + 24 + gid) * 8 + 2 * tig];
#pragma unroll
            for (int jj = 0; jj < 4; jj++) {
                uint2 wf = wip[(jj * 16 + ks) * 32];
                hmma(Ci[0][jj], fa0.x, fb0.x, fa0.y, fb0.y, wf.x, wf.y);
                hmma(Ci[1][jj], fa1.x, fb1.x, fa1.y, fb1.y, wf.x, wf.y);
            }
        }
        // epilogue: h -> uA fp16, c -> regs
#pragma unroll
        for (int mi = 0; mi < 2; mi++)
#pragma unroll
            for (int jj = 0; jj < 4; jj++) {
                int u = w * 16 + 4 * jj + tig;
                int kt = INDIM + u;
                u32 hb = ua32 + (((kt >> 4) * MT) * 8 + slotof((kt & 15) >> 1)) * 4 + (kt & 1) * 2;
                int r0 = mi * 16 + gid;
                unsigned short h0 = __half_as_ushort(__float2half_rn(Ci[mi][jj][0]));
                unsigned short h1 = __half_as_ushort(__float2half_rn(Ci[mi][jj][2]));
                asm volatile("st.shared.u16 [%0], %1;" :: "r"(hb + r0 * 32), "h"(h0));
                asm volatile("st.shared.u16 [%0], %1;" :: "r"(hb + (r0 + 8) * 32), "h"(h1));
                c[jj * 4 + mi * 2 + 0] = Ci[mi][jj][1];
                c[jj * 4 + mi * 2 + 1] = Ci[mi][jj][3];
            }
    }

    const float2* bfp = (const float2*)g_bf + (w * 8) * 32 + lane;
    const uint4*  wbp = (const uint4*)g_wb + (w * 8) * 11 * 32 + lane;
    const uint2*  wyp = (const uint2*)g_wy + (w * 17) * 32 + lane;   // only valid w<9
    float2 ybb = make_float2(0.f, 0.f);
    if (w < 9) ybb = *(const float2*)&bo[w * 8 + 2 * tig];

    for (int step = 0; step < 8; step++) {
        __syncthreads();                       // x/h stores visible

        // ---- gates GEMM ----
        float C[2][8][4];
#pragma unroll
        for (int q = 0; q < 8; q++) {
            float2 bb = bfp[q * 32];
#pragma unroll
            for (int mi = 0; mi < 2; mi++) {
                C[mi][q][0] = bb.x; C[mi][q][1] = bb.y;
                C[mi][q][2] = bb.x; C[mi][q][3] = bb.y;
            }
        }
#pragma unroll
        for (int ks2 = 0; ks2 < 11; ks2++) {
            int ks0 = 2 * ks2;
            uint2 fa0 = *(const uint2*)&uaw[(ks0 * MT + gid) * 8 + 2 * tig];
            uint2 fb0 = *(const uint2*)&uaw[(ks0 * MT + gid + 8) * 8 + 2 * tig];
            uint2 fa1 = *(const uint2*)&uaw[(ks0 * MT + 16 + gid) * 8 + 2 * tig];
            uint2 fb1 = *(const uint2*)&uaw[(ks0 * MT + 24 + gid) * 8 + 2 * tig];
            uint2 ga0, gb0, ga1, gb1;
            if (ks2 < 10) {
                ga0 = *(const uint2*)&uaw[((ks0 + 1) * MT + gid) * 8 + 2 * tig];
                gb0 = *(const uint2*)&uaw[((ks0 + 1) * MT + gid + 8) * 8 + 2 * tig];
                ga1 = *(const uint2*)&uaw[((ks0 + 1) * MT + 16 + gid) * 8 + 2 * tig];
                gb1 = *(const uint2*)&uaw[((ks0 + 1) * MT + 24 + gid) * 8 + 2 * tig];
            }
#pragma unroll
            for (int q = 0; q < 8; q++) {
                uint4 wf = wbp[(q * 11 + ks2) * 32];
                hmma(C[0][q], fa0.x, fb0.x, fa0.y, fb0.y, wf.x, wf.y);
                hmma(C[1][q], fa1.x, fb1.x, fa1.y, fb1.y, wf.x, wf.y);
                if (ks2 < 10) {
                    hmma(C[0][q], ga0.x, gb0.x, ga0.y, gb0.y, wf.z, wf.w);
                    hmma(C[1][q], ga1.x, gb1.x, ga1.y, gb1.y, wf.z, wf.w);
                }
            }
        }
        __syncthreads();                       // all uA reads complete

        // ---- elementwise LSTM cell (all in registers) ----
#pragma unroll
        for (int mi = 0; mi < 2; mi++)
#pragma unroll
            for (int jj = 0; jj < 4; jj++) {
                const float* IF = C[mi][jj * 2 + 0];   // i,f
                const float* GO = C[mi][jj * 2 + 1];   // g,o
                int u = w * 16 + 4 * jj + tig;
                int kt = INDIM + u;
                u32 hb = ua32 + (((kt >> 4) * MT) * 8 + slotof((kt & 15) >> 1)) * 4 + (kt & 1) * 2;
                int r0 = mi * 16 + gid;
#pragma unroll
                for (int r = 0; r < 2; r++) {
                    float iv = siga(IF[2 * r]);
                    float fv = siga(IF[2 * r + 1]);
                    float gv = tanha(GO[2 * r]);
                    float ov = siga(GO[2 * r + 1]);
                    float cc = fmaf(fv, c[jj * 4 + mi * 2 + r], iv * gv);
                    c[jj * 4 + mi * 2 + r] = cc;
                    float h = ov * tanha(cc);
                    unsigned short hr = __half_as_ushort(__float2half_rn(h));
                    asm volatile("st.shared.u16 [%0], %1;"
                                 :: "r"(hb + (r0 + r * 8) * 32), "h"(hr));
                }
            }
        __syncthreads();                       // h visible

        // ---- y-GEMM (warps 0..8): y = sigmoid(h @ Wo^T + bo) ----
        if (w < 9) {
            float Y[2][4];
#pragma unroll
            for (int mi = 0; mi < 2; mi++) {
                Y[mi][0] = ybb.x; Y[mi][1] = ybb.y;
                Y[mi][2] = ybb.x; Y[mi][3] = ybb.y;
            }
#pragma unroll
            for (int ky = 0; ky < 17; ky++) {
                int ks = ky + 4;
                uint2 fa0 = *(const uint2*)&uaw[(ks * MT + gid) * 8 + 2 * tig];
                uint2 fb0 = *(const uint2*)&uaw[(ks * MT + gid + 8) * 8 + 2 * tig];
                uint2 fa1 = *(const uint2*)&uaw[(ks * MT + 16 + gid) * 8 + 2 * tig];
                uint2 fb1 = *(const uint2*)&uaw[(ks * MT + 24 + gid) * 8 + 2 * tig];
                uint2 wf = wyp[ky * 32];
                hmma(Y[0], fa0.x, fb0.x, fa0.y, fb0.y, wf.x, wf.y);
                hmma(Y[1], fa1.x, fb1.x, fa1.y, fb1.y, wf.x, wf.y);
            }
            int col = w * 8 + 2 * tig;
            int ksx = col >> 4;
            int slx = slotof((col & 15) >> 1);
#pragma unroll
            for (int mi = 0; mi < 2; mi++) {
                float y0 = siga(Y[mi][0]), y1 = siga(Y[mi][1]);
                float y2 = siga(Y[mi][2]), y3 = siga(Y[mi][3]);
                int r0 = mi * 16 + gid;
                size_t ob0 = ((size_t)(m0 + r0) * 8 + step) * INDIM + col;
                size_t ob1 = ((size_t)(m0 + r0 + 8) * 8 + step) * INDIM + col;
                *(float2*)&out[ob0] = make_float2(y0, y1);
                *(float2*)&out[ob1] = make_float2(y2, y3);
                __half2 xa = __floats2half2_rn(y0, y1);
                __half2 xb = __floats2half2_rn(y2, y3);
                uaw[(ksx * MT + r0) * 8 + slx]     = *reinterpret_cast<u32*>(&xa);
                uaw[(ksx * MT + r0 + 8) * 8 + slx] = *reinterpret_cast<u32*>(&xb);
            }
        }
    }
}

extern "C" void kernel_launch(void* const* d_in, const int* in_sizes, int n_in,
                              void* d_out, int out_size) {
    const float* z    = (const float*)d_in[0];
    const float* W_ih = (const float*)d_in[1];
    const float* W_hh = (const float*)d_in[2];
    const float* b_ih = (const float*)d_in[3];
    const float* b_hh = (const float*)d_in[4];
    const float* Wh   = (const float*)d_in[5];
    const float* bh   = (const float*)d_in[6];
    const float* Wc   = (const float*)d_in[7];
    const float* bc   = (const float*)d_in[8];
    const float* Wo   = (const float*)d_in[9];
    const float* bo   = (const float*)d_in[10];
    float* out = (float*)d_out;

    int B = in_sizes[0] / HIDDEN;   // z is (1, B, 256)

    prep_kernel<<<512, 256>>>(W_ih, W_hh, b_ih, b_hh, Wh, Wc, Wo, bh, bc);
    lstm_main<<<B / MT, NT>>>(z, bo, out);
}

// round 14
// speedup vs baseline: 9.5767x; 1.0829x over previous
#include <cuda_runtime.h>
#include <cuda_fp16.h>

typedef unsigned int u32;

#define HIDDEN 256
#define INDIM  72
#define MT     32
#define NT     512
#define RS     48                  // bytes per 16-half activation row (+8 pad halfs)
#define KSB    (32*RS)             // bytes per ks-region (32 rows)

// ---------------- packed weight fragment arrays ----------------
// gates B-frags: [ntg 0..127][pp 0..11][lane] x 8 halfs (uint4)
//   pp 0..7  : phase-A ks pairs (5+2p, 6+2p)
//   pp 8     : ks4, h-half real / x-cols zeroed (phase A)
//   pp 9,10  : phase-B ks pairs (0,1),(2,3)
//   pp 11    : ks4, x-half real / h-cols zeroed (phase B)
__device__ __align__(16) __half g_wb[128 * 12 * 32 * 8];
__device__ __align__(16) float  g_bf[128 * 32 * 2];     // gate bias C-frags
__device__ __align__(16) __half g_wi[64 * 16 * 32 * 4]; // init (h,c)-interleaved
__device__ __align__(16) float  g_bi[64 * 32 * 2];      // init bias C-frags
__device__ __align__(16) __half g_wy[9 * 17 * 32 * 4];  // y frags, ky0=ks4 (x zeroed)

#define UA_BYTES (21 * KSB)        // 32256
#define ZA_BYTES (16 * KSB)        // 24576
#define SMEM_BYTES (UA_BYTES + ZA_BYTES)

__device__ __forceinline__ void ldm4(u32 r[4], u32 a) {
    asm volatile("ldmatrix.sync.aligned.m8n8.x4.shared.b16 {%0,%1,%2,%3},[%4];"
                 : "=r"(r[0]), "=r"(r[1]), "=r"(r[2]), "=r"(r[3]) : "r"(a));
}
__device__ __forceinline__ void hmma(float C[4], const u32 A[4], u32 b0, u32 b1) {
    asm("mma.sync.aligned.m16n8k16.row.col.f32.f16.f16.f32 "
        "{%0,%1,%2,%3},{%4,%5,%6,%7},{%8,%9},{%0,%1,%2,%3};"
        : "+f"(C[0]), "+f"(C[1]), "+f"(C[2]), "+f"(C[3])
        : "r"(A[0]), "r"(A[1]), "r"(A[2]), "r"(A[3]), "r"(b0), "r"(b1));
}
__device__ __forceinline__ float tanha(float x) {
    float r; asm("tanh.approx.f32 %0,%1;" : "=f"(r) : "f"(x)); return r;
}
__device__ __forceinline__ float siga(float x) {
    return fmaf(0.5f, tanha(0.5f * x), 0.5f);
}

// ---------------- prep ----------------
__global__ void prep_kernel(const float* __restrict__ W_ih, const float* __restrict__ W_hh,
                            const float* __restrict__ b_ih, const float* __restrict__ b_hh,
                            const float* __restrict__ Wh,   const float* __restrict__ Wc,
                            const float* __restrict__ Wo,   const float* __restrict__ bh,
                            const float* __restrict__ bc) {
    const int tid = blockIdx.x * blockDim.x + threadIdx.x;
    const int stride = gridDim.x * blockDim.x;

    // gates B frags
    for (int i = tid; i < 128 * 12 * 32 * 8; i += stride) {
        int e = i & 7, lane = (i >> 3) & 31, r = i >> 8;
        int pp = r % 12, ntg = r / 12;
        int wq = ntg >> 3, q = ntg & 7, jj = q >> 1, s = q & 1;
        int T = wq * 4 + jj;
        int gid = lane >> 2, tig = lane & 3;
        int col = 8 * T + gid;
        int u = col >> 1, comp = col & 1;
        int g = s ? (comp ? 3 : 2) : (comp ? 1 : 0);   // i,f,g,o torch order
        int n = g * 256 + u;
        int khalf = 2 * tig + (e & 1) + 8 * ((e >> 1) & 1);
        float v = 0.0f;
        int ks = -1, mode = 0;                         // mode 1: zero x, 2: zero h
        if (pp < 8)       { ks = 5 + 2 * pp + (e >> 2); }
        else if (pp == 8) { if (e < 4) { ks = 4; mode = 1; } }
        else if (pp < 11) { ks = 2 * (pp - 9) + (e >> 2); }
        else              { if (e < 4) { ks = 4; mode = 2; } }
        if (ks >= 0) {
            int k = ks * 16 + khalf;
            if (k < 328) {
                bool isx = (k < INDIM);
                if (!((mode == 1 && isx) || (mode == 2 && !isx)))
                    v = isx ? W_ih[n * INDIM + k] : W_hh[n * HIDDEN + (k - INDIM)];
            }
        }
        g_wb[i] = __float2half(v);
    }
    // gates bias frags
    for (int i = tid; i < 128 * 64; i += stride) {
        int e = i & 1, lane = (i >> 1) & 31, ntg = i >> 6;
        int wq = ntg >> 3, q = ntg & 7, jj = q >> 1, s = q & 1;
        int T = wq * 4 + jj;
        int tig = lane & 3;
        int col = 8 * T + 2 * tig + e;
        int u = col >> 1, comp = col & 1;
        int g = s ? (comp ? 3 : 2) : (comp ? 1 : 0);
        int n = g * 256 + u;
        g_bf[i] = b_ih[n] + b_hh[n];
    }
    // init B frags: (h,c) interleaved columns
    for (int i = tid; i < 64 * 16 * 32 * 4; i += stride) {
        int e = i & 3, lane = (i >> 2) & 31, r = i >> 7;
        int ks = r & 15, T = r >> 4;
        int gid = lane >> 2, tig = lane & 3;
        int col = 8 * T + gid;
        int u = col >> 1, comp = col & 1;
        int k = ks * 16 + 2 * tig + (e & 1) + 8 * (e >> 1);
        float v = comp ? Wc[u * HIDDEN + k] : Wh[u * HIDDEN + k];
        g_wi[i] = __float2half(v);
    }
    // init bias frags
    for (int i = tid; i < 64 * 64; i += stride) {
        int e = i & 1, lane = (i >> 1) & 31, T = i >> 6;
        int tig = lane & 3;
        int col = 8 * T + 2 * tig + e;
        int u = col >> 1, comp = col & 1;
        g_bi[i] = comp ? bc[u] : bh[u];
    }
    // y B frags (ky = ks-4, x cols / out-of-range zeroed)
    for (int i = tid; i < 9 * 17 * 32 * 4; i += stride) {
        int e = i & 3, lane = (i >> 2) & 31, r = i >> 7;
        int ky = r % 17, nt = r / 17;
        int gid = lane >> 2, tig = lane & 3;
        int k = (ky + 4) * 16 + 2 * tig + (e & 1) + 8 * (e >> 1);
        int kw = k - INDIM;
        int n = nt * 8 + gid;
        float v = (kw >= 0 && kw < HIDDEN) ? Wo[n * HIDDEN + kw] : 0.0f;
        g_wy[i] = __float2half(v);
    }
}

// ---------------- fused LSTM main ----------------
__global__ void __launch_bounds__(NT, 1)
lstm_main(const float* __restrict__ z, const float* __restrict__ bo,
          float* __restrict__ out) {
    extern __shared__ __align__(16) char sm[];
    u32* smw = (u32*)sm;
    const u32 ua32 = (u32)__cvta_generic_to_shared(sm);
    const u32 za32 = ua32 + UA_BYTES;

    const int tid  = threadIdx.x;
    const int m0   = blockIdx.x * MT;
    const int lane = tid & 31;
    const int w    = tid >> 5;
    const int gid  = lane >> 2;
    const int tig  = lane & 3;

    // ldmatrix lane address offset within a ks-region (m-tile0; tile1 = +16*RS)
    const int g8 = lane >> 3, ri = lane & 7;
    const u32 aoff = (u32)(((g8 & 1) * 8 + ri) * RS + (g8 >> 1) * 16);

    // ---- zero uA; stage z into zA (linear fp16 rows) ----
    for (int i = tid; i < UA_BYTES / 4; i += NT) smw[i] = 0u;
    for (int ii = tid; ii < MT * 128; ii += NT) {
        int m = ii >> 7, k2 = ii & 127;
        float2 zv = *(const float2*)&z[(size_t)(m0 + m) * HIDDEN + 2 * k2];
        __half2 hv = __floats2half2_rn(zv.x, zv.y);
        smw[UA_BYTES / 4 + (k2 >> 3) * 384 + m * 12 + (k2 & 7)] =
            *reinterpret_cast<u32*>(&hv);
    }
    __syncthreads();

    // ---- init GEMM: (h,c) pairs land in owner registers ----
    float c[16];
    {
        float Ci[2][4][4];
#pragma unroll
        for (int jj = 0; jj < 4; jj++) {
            float2 bb = *(const float2*)&g_bi[((w * 4 + jj) * 32 + lane) * 2];
#pragma unroll
            for (int mi = 0; mi < 2; mi++) {
                Ci[mi][jj][0] = bb.x; Ci[mi][jj][1] = bb.y;
                Ci[mi][jj][2] = bb.x; Ci[mi][jj][3] = bb.y;
            }
        }
        const uint2* wip = (const uint2*)g_wi + (w * 4) * 16 * 32 + lane;
#pragma unroll
        for (int ks = 0; ks < 16; ks++) {
            u32 A0[4], A1[4];
            ldm4(A0, za32 + ks * KSB + aoff);
            ldm4(A1, za32 + ks * KSB + 16 * RS + aoff);
#pragma unroll
            for (int jj = 0; jj < 4; jj++) {
                uint2 wf = wip[(jj * 16 + ks) * 32];
                hmma(Ci[0][jj], A0, wf.x, wf.y);
                hmma(Ci[1][jj], A1, wf.x, wf.y);
            }
        }
#pragma unroll
        for (int mi = 0; mi < 2; mi++)
#pragma unroll
            for (int jj = 0; jj < 4; jj++) {
                int u = w * 16 + 4 * jj + tig;
                int kt = INDIM + u;
                u32 hb = ua32 + (kt >> 4) * KSB + (kt & 15) * 2;
                int r0 = mi * 16 + gid;
                unsigned short h0 = __half_as_ushort(__float2half_rn(Ci[mi][jj][0]));
                unsigned short h1 = __half_as_ushort(__float2half_rn(Ci[mi][jj][2]));
                asm volatile("st.shared.u16 [%0], %1;" :: "r"(hb + r0 * RS), "h"(h0));
                asm volatile("st.shared.u16 [%0], %1;" :: "r"(hb + (r0 + 8) * RS), "h"(h1));
                c[jj * 4 + mi * 2 + 0] = Ci[mi][jj][1];
                c[jj * 4 + mi * 2 + 1] = Ci[mi][jj][3];
            }
    }

    const float2* bfp = (const float2*)g_bf + (w * 8) * 32 + lane;
    const uint4*  wbp = (const uint4*)g_wb + (w * 8) * 12 * 32 + lane;
    const uint2*  wyp = (const uint2*)g_wy + (w * 17) * 32 + lane;  // valid for w<9
    float2 ybb = make_float2(0.f, 0.f);
    if (w < 9) ybb = *(const float2*)&bo[w * 8 + 2 * tig];
    const int ycol = w * 8 + 2 * tig;
    const u32 yxaddr = ua32 + (ycol >> 4) * KSB + (ycol & 15) * 2;

    __syncthreads();   // h0, x0(=0) visible

    for (int step = 0; step < 8; step++) {
        // ================= phase A: gates h-part + y(step-1) =================
        float C[2][8][4];
#pragma unroll
        for (int q = 0; q < 8; q++) {
            float2 bb = bfp[q * 32];
#pragma unroll
            for (int mi = 0; mi < 2; mi++) {
                C[mi][q][0] = bb.x; C[mi][q][1] = bb.y;
                C[mi][q][2] = bb.x; C[mi][q][3] = bb.y;
            }
        }
        float Y[2][4];
        const bool doy = (w < 9) && (step > 0);
        if (doy) {
#pragma unroll
            for (int mi = 0; mi < 2; mi++) {
                Y[mi][0] = ybb.x; Y[mi][1] = ybb.y;
                Y[mi][2] = ybb.x; Y[mi][3] = ybb.y;
            }
        }
        // ks4 (h-half): shared A-frags for gates(pp8) and y ky0
        {
            u32 A0[4], A1[4];
            ldm4(A0, ua32 + 4 * KSB + aoff);
            ldm4(A1, ua32 + 4 * KSB + 16 * RS + aoff);
#pragma unroll
            for (int q = 0; q < 8; q++) {
                uint4 wf = wbp[(q * 12 + 8) * 32];
                hmma(C[0][q], A0, wf.x, wf.y);
                hmma(C[1][q], A1, wf.x, wf.y);
            }
            if (doy) {
                uint2 wy = wyp[0];
                hmma(Y[0], A0, wy.x, wy.y);
                hmma(Y[1], A1, wy.x, wy.y);
            }
        }
#pragma unroll
        for (int p = 0; p < 8; p++) {
            const int ksa = 5 + 2 * p;
            u32 A0a[4], A1a[4], A0b[4], A1b[4];
            ldm4(A0a, ua32 + ksa * KSB + aoff);
            ldm4(A1a, ua32 + ksa * KSB + 16 * RS + aoff);
            ldm4(A0b, ua32 + (ksa + 1) * KSB + aoff);
            ldm4(A1b, ua32 + (ksa + 1) * KSB + 16 * RS + aoff);
#pragma unroll
            for (int q = 0; q < 8; q++) {
                uint4 wf = wbp[(q * 12 + p) * 32];
                hmma(C[0][q], A0a, wf.x, wf.y);
                hmma(C[1][q], A1a, wf.x, wf.y);
                hmma(C[0][q], A0b, wf.z, wf.w);
                hmma(C[1][q], A1b, wf.z, wf.w);
            }
            if (doy) {
                uint2 w0 = wyp[(ksa - 4) * 32];
                uint2 w1 = wyp[(ksa - 3) * 32];
                hmma(Y[0], A0a, w0.x, w0.y);
                hmma(Y[1], A1a, w0.x, w0.y);
                hmma(Y[0], A0b, w1.x, w1.y);
                hmma(Y[1], A1b, w1.x, w1.y);
            }
        }
        // y epilogue: out store (step-1) + x feedback
        if (doy) {
#pragma unroll
            for (int mi = 0; mi < 2; mi++) {
                float y0 = siga(Y[mi][0]), y1 = siga(Y[mi][1]);
                float y2 = siga(Y[mi][2]), y3 = siga(Y[mi][3]);
                int r0 = mi * 16 + gid;
                size_t ob0 = ((size_t)(m0 + r0) * 8 + (step - 1)) * INDIM + ycol;
                size_t ob1 = ((size_t)(m0 + r0 + 8) * 8 + (step - 1)) * INDIM + ycol;
                *(float2*)&out[ob0] = make_float2(y0, y1);
                *(float2*)&out[ob1] = make_float2(y2, y3);
                __half2 xa = __floats2half2_rn(y0, y1);
                __half2 xb = __floats2half2_rn(y2, y3);
                asm volatile("st.shared.u32 [%0], %1;"
                             :: "r"(yxaddr + r0 * RS), "r"(*reinterpret_cast<u32*>(&xa)));
                asm volatile("st.shared.u32 [%0], %1;"
                             :: "r"(yxaddr + (r0 + 8) * RS), "r"(*reinterpret_cast<u32*>(&xb)));
            }
        }
        __syncthreads();   // x complete before phase B reads it

        // ================= phase B: gates x-part =================
#pragma unroll
        for (int pb = 0; pb < 2; pb++) {
            const int ks0 = 2 * pb;
            u32 A0a[4], A1a[4], A0b[4], A1b[4];
            ldm4(A0a, ua32 + ks0 * KSB + aoff);
            ldm4(A1a, ua32 + ks0 * KSB + 16 * RS + aoff);
            ldm4(A0b, ua32 + (ks0 + 1) * KSB + aoff);
            ldm4(A1b, ua32 + (ks0 + 1) * KSB + 16 * RS + aoff);
#pragma unroll
            for (int q = 0; q < 8; q++) {
                uint4 wf = wbp[(q * 12 + 9 + pb) * 32];
                hmma(C[0][q], A0a, wf.x, wf.y);
                hmma(C[1][q], A1a, wf.x, wf.y);
                hmma(C[0][q], A0b, wf.z, wf.w);
                hmma(C[1][q], A1b, wf.z, wf.w);
            }
        }
        {   // ks4 x-half
            u32 A0[4], A1[4];
            ldm4(A0, ua32 + 4 * KSB + aoff);
            ldm4(A1, ua32 + 4 * KSB + 16 * RS + aoff);
#pragma unroll
            for (int q = 0; q < 8; q++) {
                uint4 wf = wbp[(q * 12 + 11) * 32];
                hmma(C[0][q], A0, wf.x, wf.y);
                hmma(C[1][q], A1, wf.x, wf.y);
            }
        }

        // ---- elementwise LSTM cell (registers; h -> uA) ----
#pragma unroll
        for (int mi = 0; mi < 2; mi++)
#pragma unroll
            for (int jj = 0; jj < 4; jj++) {
                const float* IF = C[mi][jj * 2 + 0];
                const float* GO = C[mi][jj * 2 + 1];
                int u = w * 16 + 4 * jj + tig;
                int kt = INDIM + u;
                u32 hb = ua32 + (kt >> 4) * KSB + (kt & 15) * 2;
                int r0 = mi * 16 + gid;
#pragma unroll
                for (int r = 0; r < 2; r++) {
                    float iv = siga(IF[2 * r]);
                    float fv = siga(IF[2 * r + 1]);
                    float gv = tanha(GO[2 * r]);
                    float ov = siga(GO[2 * r + 1]);
                    float cc = fmaf(fv, c[jj * 4 + mi * 2 + r], iv * gv);
                    c[jj * 4 + mi * 2 + r] = cc;
                    float h = ov * tanha(cc);
                    unsigned short hr = __half_as_ushort(__float2half_rn(h));
                    asm volatile("st.shared.u16 [%0], %1;"
                                 :: "r"(hb + (r0 + r * 8) * RS), "h"(hr));
                }
            }
        __syncthreads();   // h complete before next phase A / final y
    }

    // ---- final y(7): out store only ----
    if (w < 9) {
        float Y[2][4];
#pragma unroll
        for (int mi = 0; mi < 2; mi++) {
            Y[mi][0] = ybb.x; Y[mi][1] = ybb.y;
            Y[mi][2] = ybb.x; Y[mi][3] = ybb.y;
        }
#pragma unroll
        for (int ky = 0; ky < 17; ky++) {
            int ks = ky + 4;
            u32 A0[4], A1[4];
            ldm4(A0, ua32 + ks * KSB + aoff);
            ldm4(A1, ua32 + ks * KSB + 16 * RS + aoff);
            uint2 wy = wyp[ky * 32];
            hmma(Y[0], A0, wy.x, wy.y);
            hmma(Y[1], A1, wy.x, wy.y);
        }
#pragma unroll
        for (int mi = 0; mi < 2; mi++) {
            float y0 = siga(Y[mi][0]), y1 = siga(Y[mi][1]);
            float y2 = siga(Y[mi][2]), y3 = siga(Y[mi][3]);
            int r0 = mi * 16 + gid;
            size_t ob0 = ((size_t)(m0 + r0) * 8 + 7) * INDIM + ycol;
            size_t ob1 = ((size_t)(m0 + r0 + 8) * 8 + 7) * INDIM + ycol;
            *(float2*)&out[ob0] = make_float2(y0, y1);
            *(float2*)&out[ob1] = make_float2(y2, y3);
        }
    }
}

extern "C" void kernel_launch(void* const* d_in, const int* in_sizes, int n_in,
                              void* d_out, int out_size) {
    const float* z    = (const float*)d_in[0];
    const float* W_ih = (const float*)d_in[1];
    const float* W_hh = (const float*)d_in[2];
    const float* b_ih = (const float*)d_in[3];
    const float* b_hh = (const float*)d_in[4];
    const float* Wh   = (const float*)d_in[5];
    const float* bh   = (const float*)d_in[6];
    const float* Wc   = (const float*)d_in[7];
    const float* bc   = (const float*)d_in[8];
    const float* Wo   = (const float*)d_in[9];
    const float* bo   = (const float*)d_in[10];
    float* out = (float*)d_out;

    int B = in_sizes[0] / HIDDEN;   // z is (1, B, 256)

    cudaFuncSetAttribute(lstm_main, cudaFuncAttributeMaxDynamicSharedMemorySize, SMEM_BYTES);
    prep_kernel<<<512, 256>>>(W_ih, W_hh, b_ih, b_hh, Wh, Wc, Wo, bh, bc);
    lstm_main<<<B / MT, NT, SMEM_BYTES>>>(z, bo, out);
}